// round 4
// baseline (speedup 1.0000x reference)
#include <cuda_runtime.h>
#include <cuda_bf16.h>

#define N_COARSE 100000
#define M_FINE   400000
#define C_IN     32
#define C_HID    64
#define C_OUT    32
#define K3       27

typedef unsigned long long ull;

// ---------------- scratch (static device globals; no allocation) ----------------
__device__ float g_bufA[N_COARSE * C_HID];   // 25.6 MB
__device__ float g_bufB[N_COARSE * C_HID];   // 25.6 MB
__device__ int   g_cnt[8];
__device__ int   g_list[8 * M_FINE];         // 12.8 MB bucket lists

// ---------------- helpers ----------------
__device__ __forceinline__ ull ffma2(ull a, ull b, ull c) {
    ull d;
    asm("fma.rn.f32x2 %0, %1, %2, %3;" : "=l"(d) : "l"(a), "l"(b), "l"(c));
    return d;
}
__device__ __forceinline__ ull pack2(float lo, float hi) {
    ull r;
    asm("mov.b64 %0, {%1, %2};" : "=l"(r) : "f"(lo), "f"(hi));
    return r;
}
__device__ __forceinline__ float2 unpack2(ull v) {
    float2 r;
    asm("mov.b64 {%0, %1}, %2;" : "=f"(r.x), "=f"(r.y) : "l"(v));
    return r;
}
__device__ __forceinline__ unsigned smem_u32(const void* p) {
    return (unsigned)__cvta_generic_to_shared(p);
}
__device__ __forceinline__ void cp_async16(unsigned dst, const void* src, int src_bytes) {
    asm volatile("cp.async.cg.shared.global [%0], [%1], 16, %2;"
                 :: "r"(dst), "l"(src), "r"(src_bytes));
}

// ---------------- reset + bucket (group fine voxels by t-conv offset) ----------------
__global__ void reset_kernel() {
    if (threadIdx.x < 8) g_cnt[threadIdx.x] = 0;
}

__global__ void __launch_bounds__(256)
bucket_kernel(const int* __restrict__ offs) {
    int m = blockIdx.x * 256 + threadIdx.x;
    unsigned active = __ballot_sync(0xffffffffu, m < M_FINE);
    if (m < M_FINE) {
        int off = offs[m] & 7;
        unsigned mask = __match_any_sync(active, off);
        int lane = threadIdx.x & 31;
        int leader = __ffs(mask) - 1;
        int rank = __popc(mask & ((1u << lane) - 1u));
        int base = 0;
        if (lane == leader) base = atomicAdd(&g_cnt[off], __popc(mask));
        base = __shfl_sync(mask, base, leader);
        g_list[off * M_FINE + base + rank] = m;
    }
}

// ---------------- sparse 3x3x3 conv ----------------
// 128 threads, 128-voxel tile; thread = 8 voxels x 8 couts (couts tx*4 and 32+tx*4).
// x gathered via cp.async (.cg, L2-only) double-buffered in smem (broadcast reads,
// no padding needed). Weights + nbr read via LDG through L1.
template <int CIN>
__global__ void __launch_bounds__(128)
conv3_tile(const float* __restrict__ x, const int* __restrict__ nbr,
           const float* __restrict__ W, const float* __restrict__ b,
           float* __restrict__ out) {
    constexpr int TILE = 128;
    constexpr int CH4 = CIN / 4;          // 16B chunks per voxel
    extern __shared__ float sX[];          // [2][TILE*CIN]

    const int tid = threadIdx.x;
    const int tx  = tid & 7;
    const int ty  = tid >> 3;              // 0..15, voxels ty*8..ty*8+7
    const int vb  = blockIdx.x * TILE;

    auto issue = [&](int k, int buf) {
        float* xd = sX + buf * TILE * CIN;
        #pragma unroll
        for (int r = 0; r < (TILE * CH4) / 128; ++r) {
            int i = tid + 128 * r;
            int v = i / CH4, c4 = i % CH4;     // CH4 is 8 or 16 -> shifts
            int gv = vb + v;
            int idx = (gv < N_COARSE) ? __ldg(nbr + gv * K3 + k) : N_COARSE;
            bool ok = idx < N_COARSE;
            const float* src = ok ? (x + idx * CIN + c4 * 4) : x;
            cp_async16(smem_u32(xd + v * CIN + c4 * 4), src, ok ? 16 : 0);
        }
        asm volatile("cp.async.commit_group;");
    };

    ull acc[32];
    #pragma unroll
    for (int i = 0; i < 32; ++i) acc[i] = 0ull;

    issue(0, 0);
    for (int k = 0; k < K3; ++k) {
        if (k < K3 - 1) {
            issue(k + 1, (k + 1) & 1);
            asm volatile("cp.async.wait_group 1;");
        } else {
            asm volatile("cp.async.wait_group 0;");
        }
        __syncthreads();
        const float* cx = sX + (k & 1) * TILE * CIN;
        const float* Wk = W + k * CIN * 64;
        #pragma unroll
        for (int c = 0; c < CIN; c += 4) {
            float4 xs[8];
            #pragma unroll
            for (int i = 0; i < 8; ++i)
                xs[i] = *(const float4*)(cx + (ty * 8 + i) * CIN + c);
            #pragma unroll
            for (int cc = 0; cc < 4; ++cc) {
                float4 wA = __ldg((const float4*)(Wk + (c + cc) * 64 + tx * 4));
                float4 wB = __ldg((const float4*)(Wk + (c + cc) * 64 + 32 + tx * 4));
                ull wa0 = pack2(wA.x, wA.y), wa1 = pack2(wA.z, wA.w);
                ull wb0 = pack2(wB.x, wB.y), wb1 = pack2(wB.z, wB.w);
                #pragma unroll
                for (int i = 0; i < 8; ++i) {
                    float xv = ((const float*)&xs[i])[cc];
                    ull xx = pack2(xv, xv);
                    acc[4 * i + 0] = ffma2(xx, wa0, acc[4 * i + 0]);
                    acc[4 * i + 1] = ffma2(xx, wa1, acc[4 * i + 1]);
                    acc[4 * i + 2] = ffma2(xx, wb0, acc[4 * i + 2]);
                    acc[4 * i + 3] = ffma2(xx, wb1, acc[4 * i + 3]);
                }
            }
        }
        __syncthreads();
    }

    float4 bA = __ldg((const float4*)(b + tx * 4));
    float4 bB = __ldg((const float4*)(b + 32 + tx * 4));
    #pragma unroll
    for (int i = 0; i < 8; ++i) {
        int v = vb + ty * 8 + i;
        if (v < N_COARSE) {
            float2 rA0 = unpack2(acc[4 * i + 0]);
            float2 rA1 = unpack2(acc[4 * i + 1]);
            float2 rB0 = unpack2(acc[4 * i + 2]);
            float2 rB1 = unpack2(acc[4 * i + 3]);
            float4 oA = make_float4(fmaxf(rA0.x + bA.x, 0.f), fmaxf(rA0.y + bA.y, 0.f),
                                    fmaxf(rA1.x + bA.z, 0.f), fmaxf(rA1.y + bA.w, 0.f));
            float4 oB = make_float4(fmaxf(rB0.x + bB.x, 0.f), fmaxf(rB0.y + bB.y, 0.f),
                                    fmaxf(rB1.x + bB.z, 0.f), fmaxf(rB1.y + bB.w, 0.f));
            *(float4*)(out + v * 64 + tx * 4)      = oA;
            *(float4*)(out + v * 64 + 32 + tx * 4) = oB;
        }
    }
}

// ---------------- shared 64x64 GEMM + bias + relu; weights direct from global (L1) ----------------
__device__ __forceinline__ void gemm64x64_relu(const float* __restrict__ sx,
                                               const float* __restrict__ gw,
                                               const float* __restrict__ sb,
                                               float* __restrict__ so,
                                               int tx, int ty) {
    ull acc[8];
    #pragma unroll
    for (int i = 0; i < 8; ++i) acc[i] = 0ull;
    #pragma unroll
    for (int c = 0; c < 64; c += 4) {
        float4 xs[4];
        #pragma unroll
        for (int i = 0; i < 4; ++i)
            xs[i] = *(const float4*)(sx + (ty * 4 + i) * 68 + c);
        #pragma unroll
        for (int cc = 0; cc < 4; ++cc) {
            float4 w = __ldg((const float4*)(gw + (c + cc) * 64 + tx * 4));
            ull w01 = pack2(w.x, w.y), w23 = pack2(w.z, w.w);
            #pragma unroll
            for (int i = 0; i < 4; ++i) {
                float xv = ((const float*)&xs[i])[cc];
                ull xx = pack2(xv, xv);
                acc[2 * i]     = ffma2(xx, w01, acc[2 * i]);
                acc[2 * i + 1] = ffma2(xx, w23, acc[2 * i + 1]);
            }
        }
    }
    float2 b01 = *(const float2*)(sb + tx * 4);
    float2 b23 = *(const float2*)(sb + tx * 4 + 2);
    #pragma unroll
    for (int i = 0; i < 4; ++i) {
        float2 r01 = unpack2(acc[2 * i]);
        float2 r23 = unpack2(acc[2 * i + 1]);
        float4 o = make_float4(fmaxf(r01.x + b01.x, 0.f), fmaxf(r01.y + b01.y, 0.f),
                               fmaxf(r23.x + b23.x, 0.f), fmaxf(r23.y + b23.y, 0.f));
        *(float4*)(so + (ty * 4 + i) * 68 + tx * 4) = o;
    }
}

// ---------------- fused t-conv + decoder: per-offset bucketed GEMM pipeline ----------------
__global__ void __launch_bounds__(256)
fused_kernel(const float* __restrict__ x3, const int* __restrict__ parent,
             const float* __restrict__ Wt, const float* __restrict__ bt,
             const float* __restrict__ Wd1, const float* __restrict__ bd1,
             const float* __restrict__ Wd2, const float* __restrict__ bd2,
             const float* __restrict__ xup, float* __restrict__ out) {
    extern __shared__ float dsm[];
    float* sg  = dsm;              // 64*68
    float* st  = sg + 64 * 68;     // 64*68
    float* sbt = st + 64 * 68;     // 64
    float* sb1 = sbt + 64;         // 64
    float* sb2 = sb1 + 64;         // 32
    int*   smv = (int*)(sb2 + 32); // 64
    int*   spv = smv + 64;         // 64

    const int tid = threadIdx.x;
    const int off = blockIdx.y;
    const int cnt = g_cnt[off];
    const int* list = g_list + off * M_FINE;
    const float* Wto = Wt + off * 4096;

    if (tid < 64) { sbt[tid] = bt[tid]; sb1[tid] = bd1[tid]; }
    if (tid < 32) sb2[tid] = bd2[tid];

    const int tx = tid & 15, ty = tid >> 4;     // stage1/2 tiling
    const int tx3 = tid & 31, ty3 = tid >> 5;   // stage3 tiling

    for (int tile = blockIdx.x; tile * 64 < cnt; tile += gridDim.x) {
        __syncthreads();
        if (tid < 64) {
            int j = tile * 64 + tid;
            int m = (j < cnt) ? list[j] : -1;
            smv[tid] = m;
            spv[tid] = (m >= 0) ? parent[m] : N_COARSE;
        }
        __syncthreads();
        // gather parent features (64 rows x 64 ch)
        #pragma unroll
        for (int r = 0; r < 4; ++r) {
            int i = tid + 256 * r;
            int v = i >> 4, c4 = i & 15;
            int p = spv[v];
            float4 val = make_float4(0.f, 0.f, 0.f, 0.f);
            if (p < N_COARSE) val = *(const float4*)(x3 + p * 64 + c4 * 4);
            *(float4*)(sg + v * 68 + c4 * 4) = val;
        }
        __syncthreads();
        gemm64x64_relu(sg, Wto, sbt, st, tx, ty);   // t = relu(g @ Wt[off] + bt)
        __syncthreads();
        gemm64x64_relu(st, Wd1, sb1, sg, tx, ty);   // y = relu(t @ Wd1 + bd1)
        __syncthreads();
        // stage3: z = y @ Wd2 + bd2; out = z + xup (voxel-pair packed)
        ull a[4];
        #pragma unroll
        for (int q = 0; q < 4; ++q) a[q] = 0ull;
        #pragma unroll
        for (int c = 0; c < 64; c += 4) {
            float4 ys[8];
            #pragma unroll
            for (int j = 0; j < 8; ++j)
                ys[j] = *(const float4*)(sg + (ty3 * 8 + j) * 68 + c);
            #pragma unroll
            for (int cc = 0; cc < 4; ++cc) {
                float w = __ldg(Wd2 + (c + cc) * 32 + tx3);
                ull ww = pack2(w, w);
                #pragma unroll
                for (int q = 0; q < 4; ++q) {
                    float y0 = ((const float*)&ys[2 * q])[cc];
                    float y1 = ((const float*)&ys[2 * q + 1])[cc];
                    a[q] = ffma2(pack2(y0, y1), ww, a[q]);
                }
            }
        }
        float b2 = sb2[tx3];
        #pragma unroll
        for (int q = 0; q < 4; ++q) {
            float2 z = unpack2(a[q]);
            int v0 = ty3 * 8 + 2 * q;
            int m0 = smv[v0], m1 = smv[v0 + 1];
            if (m0 >= 0) out[m0 * 32 + tx3] = z.x + b2 + xup[m0 * 32 + tx3];
            if (m1 >= 0) out[m1 * 32 + tx3] = z.y + b2 + xup[m1 * 32 + tx3];
        }
    }
}

// ---------------- launch ----------------
extern "C" void kernel_launch(void* const* d_in, const int* in_sizes, int n_in,
                              void* d_out, int out_size) {
    const float* feats  = (const float*)d_in[0];   // [N,32]
    const float* xup    = (const float*)d_in[1];   // [M,32]
    const int*   nbr    = (const int*)d_in[2];     // [N,27]
    const int*   parent = (const int*)d_in[3];     // [M]
    const int*   offs   = (const int*)d_in[4];     // [M]
    const float* We1 = (const float*)d_in[5];
    const float* be1 = (const float*)d_in[6];
    const float* We2 = (const float*)d_in[7];
    const float* be2 = (const float*)d_in[8];
    const float* We3 = (const float*)d_in[9];
    const float* be3 = (const float*)d_in[10];
    const float* Wt  = (const float*)d_in[11];
    const float* bt  = (const float*)d_in[12];
    const float* Wd1 = (const float*)d_in[13];
    const float* bd1 = (const float*)d_in[14];
    const float* Wd2 = (const float*)d_in[15];
    const float* bd2 = (const float*)d_in[16];
    float* out = (float*)d_out;

    float *pA, *pB;
    cudaGetSymbolAddress((void**)&pA, g_bufA);
    cudaGetSymbolAddress((void**)&pB, g_bufB);

    const int smem32 = 2 * 128 * 32 * 4;   // 32768
    const int smem64 = 2 * 128 * 64 * 4;   // 65536
    const int smemF  = (2 * 64 * 68 + 160 + 128) * 4 + 256;

    cudaFuncSetAttribute(conv3_tile<32>, cudaFuncAttributeMaxDynamicSharedMemorySize, smem32);
    cudaFuncSetAttribute(conv3_tile<64>, cudaFuncAttributeMaxDynamicSharedMemorySize, smem64);
    cudaFuncSetAttribute(fused_kernel,   cudaFuncAttributeMaxDynamicSharedMemorySize, smemF);

    reset_kernel<<<1, 32>>>();
    bucket_kernel<<<(M_FINE + 255) / 256, 256>>>(offs);

    const int nblk = (N_COARSE + 127) / 128;  // 782
    conv3_tile<32><<<nblk, 128, smem32>>>(feats, nbr, We1, be1, pA);
    conv3_tile<64><<<nblk, 128, smem64>>>(pA,    nbr, We2, be2, pB);
    conv3_tile<64><<<nblk, 128, smem64>>>(pB,    nbr, We3, be3, pA);

    fused_kernel<<<dim3(128, 8), 256, smemF>>>(pA, parent, Wt, bt, Wd1, bd1,
                                               Wd2, bd2, xup, out);
}

// round 9
// speedup vs baseline: 2.9319x; 2.9319x over previous
#include <cuda_runtime.h>
#include <cuda_bf16.h>
#include <cstdint>

#define N_COARSE 100000
#define M_FINE   400000
#define C_IN     32
#define C_HID    64
#define C_OUT    32
#define K3       27

typedef unsigned long long ull;

// ---------------- scratch (static device globals; no allocation) ----------------
__device__ float g_bufA[N_COARSE * C_HID];                  // conv3 fp32 out
__device__ __nv_bfloat16 g_xhi[N_COARSE * C_IN];
__device__ __nv_bfloat16 g_xlo[N_COARSE * C_IN];
__device__ __nv_bfloat16 g_h1hi[N_COARSE * C_HID];
__device__ __nv_bfloat16 g_h1lo[N_COARSE * C_HID];
__device__ __nv_bfloat16 g_h2hi[N_COARSE * C_HID];
__device__ __nv_bfloat16 g_h2lo[N_COARSE * C_HID];
__device__ __nv_bfloat16 g_wthi[3 * K3 * 64 * 64];          // [layer][k][cin][cout] bf16
__device__ __nv_bfloat16 g_wtlo[3 * K3 * 64 * 64];
__device__ int   g_cnt[8];
__device__ int   g_list[8 * M_FINE];

// weight element offsets per layer: l0 = 27*32*64, l1/l2 = 27*64*64
#define W_OFF1 55296
#define W_OFF2 165888
#define W_TOT  276480

// ---------------- generic helpers ----------------
__device__ __forceinline__ ull ffma2(ull a, ull b, ull c) {
    ull d;
    asm("fma.rn.f32x2 %0, %1, %2, %3;" : "=l"(d) : "l"(a), "l"(b), "l"(c));
    return d;
}
__device__ __forceinline__ ull pack2(float lo, float hi) {
    ull r;
    asm("mov.b64 %0, {%1, %2};" : "=l"(r) : "f"(lo), "f"(hi));
    return r;
}
__device__ __forceinline__ float2 unpack2(ull v) {
    float2 r;
    asm("mov.b64 {%0, %1}, %2;" : "=f"(r.x), "=f"(r.y) : "l"(v));
    return r;
}
__device__ __forceinline__ unsigned smem_u32(const void* p) {
    return (unsigned)__cvta_generic_to_shared(p);
}
__device__ __forceinline__ void cp_async16(unsigned dst, const void* src, int src_bytes) {
    asm volatile("cp.async.cg.shared.global [%0], [%1], 16, %2;"
                 :: "r"(dst), "l"(src), "r"(src_bytes));
}
__device__ __forceinline__ uint32_t sw128(uint32_t b) { return b ^ ((b >> 3) & 0x70); }

// ---------------- base-ISA tensor-core wrappers (sm_80+; no 'a' features) ----------------
__device__ __forceinline__ void ldsm_x4(uint32_t r[4], uint32_t a) {
    asm volatile("ldmatrix.sync.aligned.m8n8.x4.shared.b16 {%0,%1,%2,%3}, [%4];"
                 : "=r"(r[0]), "=r"(r[1]), "=r"(r[2]), "=r"(r[3]) : "r"(a));
}
__device__ __forceinline__ void ldsm_x2_t(uint32_t r[2], uint32_t a) {
    asm volatile("ldmatrix.sync.aligned.m8n8.x2.trans.shared.b16 {%0,%1}, [%2];"
                 : "=r"(r[0]), "=r"(r[1]) : "r"(a));
}
__device__ __forceinline__ void mma_bf16(float* d, const uint32_t* a, const uint32_t* b) {
    asm volatile("mma.sync.aligned.m16n8k16.row.col.f32.bf16.bf16.f32 "
                 "{%0,%1,%2,%3}, {%4,%5,%6,%7}, {%8,%9}, {%0,%1,%2,%3};"
                 : "+f"(d[0]), "+f"(d[1]), "+f"(d[2]), "+f"(d[3])
                 : "r"(a[0]), "r"(a[1]), "r"(a[2]), "r"(a[3]), "r"(b[0]), "r"(b[1]));
}

// ---------------- pre-pass: split fp32 -> bf16 hi/lo ----------------
__global__ void __launch_bounds__(256)
convert_feats(const float* __restrict__ x, int n,
              __nv_bfloat16* __restrict__ hi, __nv_bfloat16* __restrict__ lo) {
    int i = blockIdx.x * 256 + threadIdx.x;
    if (i < n) {
        float v = x[i];
        __nv_bfloat16 h = __float2bfloat16(v);
        hi[i] = h;
        lo[i] = __float2bfloat16(v - __bfloat162float(h));
    }
}

// weights keep their native [k][cin][cout] layout (B row-major for ldmatrix.trans)
__global__ void __launch_bounds__(256)
convert_weights(const float* __restrict__ W1, const float* __restrict__ W2,
                const float* __restrict__ W3,
                __nv_bfloat16* __restrict__ hi, __nv_bfloat16* __restrict__ lo) {
    int i = blockIdx.x * 256 + threadIdx.x;
    if (i >= W_TOT) return;
    float v;
    if (i < W_OFF1)      v = W1[i];
    else if (i < W_OFF2) v = W2[i - W_OFF1];
    else                 v = W3[i - W_OFF2];
    __nv_bfloat16 h = __float2bfloat16(v);
    hi[i] = h;
    lo[i] = __float2bfloat16(v - __bfloat162float(h));
}

// ---------------- reset + bucket ----------------
__global__ void reset_kernel() {
    if (threadIdx.x < 8) g_cnt[threadIdx.x] = 0;
}

__global__ void __launch_bounds__(256)
bucket_kernel(const int* __restrict__ offs) {
    int m = blockIdx.x * 256 + threadIdx.x;
    unsigned active = __ballot_sync(0xffffffffu, m < M_FINE);
    if (m < M_FINE) {
        int off = offs[m] & 7;
        unsigned mask = __match_any_sync(active, off);
        int lane = threadIdx.x & 31;
        int leader = __ffs(mask) - 1;
        int rank = __popc(mask & ((1u << lane) - 1u));
        int base = 0;
        if (lane == leader) base = atomicAdd(&g_cnt[off], __popc(mask));
        base = __shfl_sync(mask, base, leader);
        g_list[off * M_FINE + base + rank] = m;
    }
}

// ---------------- mma.sync sparse 3x3x3 conv ----------------
// 128-voxel tile per block, 256 threads (8 warps; warp = 16 rows x 64 couts).
// Per offset: gather A rows (hi/lo bf16, SW128) + W[k] (hi/lo, native [cin][cout])
// via cp.async double-buffer; compute with ldmatrix + mma.m16n8k16 (3 split products).
// smem: A planes 4x16KB at 0; B planes 4xBSZ at 65536.
template <int CIN, bool OUT_BF16>
__global__ void __launch_bounds__(256)
conv3_mma(const __nv_bfloat16* __restrict__ xhi, const __nv_bfloat16* __restrict__ xlo,
          const int* __restrict__ nbr,
          const __nv_bfloat16* __restrict__ whi, const __nv_bfloat16* __restrict__ wlo,
          const float* __restrict__ bias,
          __nv_bfloat16* __restrict__ ohi, __nv_bfloat16* __restrict__ olo,
          float* __restrict__ ofp) {
    constexpr int KSTEPS = CIN / 16;
    constexpr int CH = CIN / 8;            // 16B chunks per A row
    constexpr int BSZ = CIN * 128;         // bytes per B plane
    extern __shared__ char dsm[];
    const uint32_t sb = smem_u32(dsm);
    const int tid = threadIdx.x, wid = tid >> 5, lane = tid & 31;
    const int vb = blockIdx.x * 128;

    const int arow = tid >> 1, aplane = tid & 1;   // gather: thread = (row, plane)
    const int gvr = vb + arow;

    auto issue = [&](int k, int buf) {
        int idx = (gvr < N_COARSE) ? __ldg(nbr + gvr * K3 + k) : N_COARSE;
        bool ok = idx < N_COARSE;
        const char* src = (const char*)(aplane ? xlo : xhi) + (size_t)(ok ? idx : 0) * (CIN * 2);
        uint32_t ab = sb + (buf * 2 + aplane) * 16384;
        #pragma unroll
        for (int c = 0; c < CH; ++c)
            cp_async16(ab + sw128(arow * 128 + c * 16), src + c * 16, ok ? 16 : 0);
        #pragma unroll
        for (int r = 0; r < CIN / 16; ++r) {       // B: CIN rows x 8 chunks x 2 planes
            int i = tid + 256 * r;
            int brow = i >> 4, q = i & 15, bp = q >> 3, bc = q & 7;
            const char* wsrc = (const char*)(bp ? wlo : whi)
                             + (size_t)k * (CIN * 128) + brow * 128 + bc * 16;
            uint32_t bb = sb + 65536 + (buf * 2 + bp) * BSZ;
            cp_async16(bb + sw128(brow * 128 + bc * 16), wsrc, 16);
        }
        asm volatile("cp.async.commit_group;");
    };

    float acc[8][4];
    #pragma unroll
    for (int t = 0; t < 8; ++t)
        #pragma unroll
        for (int q = 0; q < 4; ++q) acc[t][q] = 0.f;

    const int lr = lane & 7, rb = (lane >> 3) & 1, kb = (lane >> 4) & 1;
    const int amrow = wid * 16 + rb * 8 + lr;      // ldmatrix A row for this lane
    const int bkl = lane & 15;                     // ldmatrix B k-row selector

    issue(0, 0);
    for (int k = 0; k < K3; ++k) {
        if (k + 1 < K3) {
            issue(k + 1, (k + 1) & 1);
            asm volatile("cp.async.wait_group 1;" ::: "memory");
        } else {
            asm volatile("cp.async.wait_group 0;" ::: "memory");
        }
        __syncthreads();
        const int buf = k & 1;
        const uint32_t ahb = sb + (buf * 2 + 0) * 16384;
        const uint32_t alb = sb + (buf * 2 + 1) * 16384;
        const uint32_t bhb = sb + 65536 + (buf * 2 + 0) * BSZ;
        const uint32_t blb = bhb + BSZ;
        #pragma unroll
        for (int ks = 0; ks < KSTEPS; ++ks) {
            uint32_t abyte = sw128(amrow * 128 + ks * 32 + kb * 16);
            uint32_t ah[4], al[4];
            ldsm_x4(ah, ahb + abyte);
            ldsm_x4(al, alb + abyte);
            int krow = ks * 16 + bkl;
            uint32_t bbase = (uint32_t)krow * 128;
            uint32_t bxor = (uint32_t)(krow & 7) << 4;
            #pragma unroll
            for (int t = 0; t < 8; ++t) {
                uint32_t bb = bbase + ((uint32_t)(t * 16) ^ bxor);
                uint32_t bh[2], bl[2];
                ldsm_x2_t(bh, bhb + bb);
                ldsm_x2_t(bl, blb + bb);
                mma_bf16(acc[t], ah, bh);   // hi*hi
                mma_bf16(acc[t], ah, bl);   // hi*lo
                mma_bf16(acc[t], al, bh);   // lo*hi
            }
        }
        __syncthreads();
    }

    // epilogue: bias + relu; emit bf16 hi/lo (layers 1-2) or fp32 (layer 3)
    #pragma unroll
    for (int t = 0; t < 8; ++t) {
        #pragma unroll
        for (int h = 0; h < 2; ++h) {
            int r = wid * 16 + (lane >> 2) + h * 8;
            int v = vb + r;
            if (v < N_COARSE) {
                int c = t * 8 + (lane & 3) * 2;
                float a0 = fmaxf(acc[t][h * 2 + 0] + __ldg(bias + c),     0.f);
                float a1 = fmaxf(acc[t][h * 2 + 1] + __ldg(bias + c + 1), 0.f);
                if (OUT_BF16) {
                    __nv_bfloat16 h0 = __float2bfloat16(a0), h1 = __float2bfloat16(a1);
                    __nv_bfloat16 l0 = __float2bfloat16(a0 - __bfloat162float(h0));
                    __nv_bfloat16 l1 = __float2bfloat16(a1 - __bfloat162float(h1));
                    __nv_bfloat162 hh = __halves2bfloat162(h0, h1);
                    __nv_bfloat162 ll = __halves2bfloat162(l0, l1);
                    *(__nv_bfloat162*)(ohi + (size_t)v * 64 + c) = hh;
                    *(__nv_bfloat162*)(olo + (size_t)v * 64 + c) = ll;
                } else {
                    *(float2*)(ofp + (size_t)v * 64 + c) = make_float2(a0, a1);
                }
            }
        }
    }
}

// ---------------- shared 64x64 GEMM + bias + relu (round-3 best) ----------------
__device__ __forceinline__ void gemm64x64_relu(const float* __restrict__ sx,
                                               const float* __restrict__ sw,
                                               const float* __restrict__ sb,
                                               float* __restrict__ so,
                                               int tx, int ty) {
    ull acc[8];
    #pragma unroll
    for (int i = 0; i < 8; ++i) acc[i] = 0ull;
    #pragma unroll
    for (int c = 0; c < 64; c += 4) {
        float4 xs[4];
        #pragma unroll
        for (int i = 0; i < 4; ++i)
            xs[i] = *(const float4*)(sx + (ty * 4 + i) * 68 + c);
        #pragma unroll
        for (int cc = 0; cc < 4; ++cc) {
            float4 w = *(const float4*)(sw + (c + cc) * 64 + tx * 4);
            ull w01 = pack2(w.x, w.y), w23 = pack2(w.z, w.w);
            #pragma unroll
            for (int i = 0; i < 4; ++i) {
                float xv = ((const float*)&xs[i])[cc];
                ull xx = pack2(xv, xv);
                acc[2 * i]     = ffma2(xx, w01, acc[2 * i]);
                acc[2 * i + 1] = ffma2(xx, w23, acc[2 * i + 1]);
            }
        }
    }
    float2 b01 = *(const float2*)(sb + tx * 4);
    float2 b23 = *(const float2*)(sb + tx * 4 + 2);
    #pragma unroll
    for (int i = 0; i < 4; ++i) {
        float2 r01 = unpack2(acc[2 * i]);
        float2 r23 = unpack2(acc[2 * i + 1]);
        float4 o = make_float4(fmaxf(r01.x + b01.x, 0.f), fmaxf(r01.y + b01.y, 0.f),
                               fmaxf(r23.x + b23.x, 0.f), fmaxf(r23.y + b23.y, 0.f));
        *(float4*)(so + (ty * 4 + i) * 68 + tx * 4) = o;
    }
}

// ---------------- fused t-conv + decoder (round-3 best) ----------------
__global__ void __launch_bounds__(256)
fused_kernel(const float* __restrict__ x3, const int* __restrict__ parent,
             const float* __restrict__ Wt, const float* __restrict__ bt,
             const float* __restrict__ Wd1, const float* __restrict__ bd1,
             const float* __restrict__ Wd2, const float* __restrict__ bd2,
             const float* __restrict__ xup, float* __restrict__ out) {
    extern __shared__ float dsmf[];
    float* sWt = dsmf;
    float* sW1 = sWt + 4096;
    float* sW2 = sW1 + 4096;
    float* sg  = sW2 + 2048;
    float* st  = sg + 64 * 68;
    float* sbt = st + 64 * 68;
    float* sb1 = sbt + 64;
    float* sb2 = sb1 + 64;
    int*   smv = (int*)(sb2 + 32);
    int*   spv = smv + 64;

    const int tid = threadIdx.x;
    const int off = blockIdx.y;
    const int cnt = g_cnt[off];
    const int* list = g_list + off * M_FINE;

    {
        const float4* w = (const float4*)(Wt + off * 4096);
        #pragma unroll
        for (int r = 0; r < 4; ++r) ((float4*)sWt)[tid + 256 * r] = w[tid + 256 * r];
        const float4* w1 = (const float4*)Wd1;
        #pragma unroll
        for (int r = 0; r < 4; ++r) ((float4*)sW1)[tid + 256 * r] = w1[tid + 256 * r];
        const float4* w2 = (const float4*)Wd2;
        #pragma unroll
        for (int r = 0; r < 2; ++r) ((float4*)sW2)[tid + 256 * r] = w2[tid + 256 * r];
        if (tid < 64) { sbt[tid] = bt[tid]; sb1[tid] = bd1[tid]; }
        if (tid < 32) sb2[tid] = bd2[tid];
    }

    const int tx = tid & 15, ty = tid >> 4;
    const int tx3 = tid & 31, ty3 = tid >> 5;

    for (int tile = blockIdx.x; tile * 64 < cnt; tile += gridDim.x) {
        __syncthreads();
        if (tid < 64) {
            int j = tile * 64 + tid;
            int m = (j < cnt) ? list[j] : -1;
            smv[tid] = m;
            spv[tid] = (m >= 0) ? parent[m] : N_COARSE;
        }
        __syncthreads();
        #pragma unroll
        for (int r = 0; r < 4; ++r) {
            int i = tid + 256 * r;
            int v = i >> 4, c4 = i & 15;
            int p = spv[v];
            float4 val = make_float4(0.f, 0.f, 0.f, 0.f);
            if (p < N_COARSE) val = *(const float4*)(x3 + p * 64 + c4 * 4);
            *(float4*)(sg + v * 68 + c4 * 4) = val;
        }
        __syncthreads();
        gemm64x64_relu(sg, sWt, sbt, st, tx, ty);
        __syncthreads();
        gemm64x64_relu(st, sW1, sb1, sg, tx, ty);
        __syncthreads();
        ull a[4];
        #pragma unroll
        for (int q = 0; q < 4; ++q) a[q] = 0ull;
        #pragma unroll
        for (int c = 0; c < 64; c += 4) {
            float4 ys[8];
            #pragma unroll
            for (int j = 0; j < 8; ++j)
                ys[j] = *(const float4*)(sg + (ty3 * 8 + j) * 68 + c);
            #pragma unroll
            for (int cc = 0; cc < 4; ++cc) {
                float w = sW2[(c + cc) * 32 + tx3];
                ull ww = pack2(w, w);
                #pragma unroll
                for (int q = 0; q < 4; ++q) {
                    float y0 = ((const float*)&ys[2 * q])[cc];
                    float y1 = ((const float*)&ys[2 * q + 1])[cc];
                    a[q] = ffma2(pack2(y0, y1), ww, a[q]);
                }
            }
        }
        float b2 = sb2[tx3];
        #pragma unroll
        for (int q = 0; q < 4; ++q) {
            float2 z = unpack2(a[q]);
            int v0 = ty3 * 8 + 2 * q;
            int m0 = smv[v0], m1 = smv[v0 + 1];
            if (m0 >= 0) out[m0 * 32 + tx3] = z.x + b2 + xup[m0 * 32 + tx3];
            if (m1 >= 0) out[m1 * 32 + tx3] = z.y + b2 + xup[m1 * 32 + tx3];
        }
    }
}

// ---------------- launch ----------------
extern "C" void kernel_launch(void* const* d_in, const int* in_sizes, int n_in,
                              void* d_out, int out_size) {
    const float* feats  = (const float*)d_in[0];
    const float* xup    = (const float*)d_in[1];
    const int*   nbr    = (const int*)d_in[2];
    const int*   parent = (const int*)d_in[3];
    const int*   offs   = (const int*)d_in[4];
    const float* We1 = (const float*)d_in[5];
    const float* be1 = (const float*)d_in[6];
    const float* We2 = (const float*)d_in[7];
    const float* be2 = (const float*)d_in[8];
    const float* We3 = (const float*)d_in[9];
    const float* be3 = (const float*)d_in[10];
    const float* Wt  = (const float*)d_in[11];
    const float* bt  = (const float*)d_in[12];
    const float* Wd1 = (const float*)d_in[13];
    const float* bd1 = (const float*)d_in[14];
    const float* Wd2 = (const float*)d_in[15];
    const float* bd2 = (const float*)d_in[16];
    float* out = (float*)d_out;

    float* pA;
    __nv_bfloat16 *xhi, *xlo, *h1hi, *h1lo, *h2hi, *h2lo, *wthi, *wtlo;
    cudaGetSymbolAddress((void**)&pA,   g_bufA);
    cudaGetSymbolAddress((void**)&xhi,  g_xhi);
    cudaGetSymbolAddress((void**)&xlo,  g_xlo);
    cudaGetSymbolAddress((void**)&h1hi, g_h1hi);
    cudaGetSymbolAddress((void**)&h1lo, g_h1lo);
    cudaGetSymbolAddress((void**)&h2hi, g_h2hi);
    cudaGetSymbolAddress((void**)&h2lo, g_h2lo);
    cudaGetSymbolAddress((void**)&wthi, g_wthi);
    cudaGetSymbolAddress((void**)&wtlo, g_wtlo);

    const int smem32 = 65536 + 4 * (32 * 128);   // 81920
    const int smem64 = 65536 + 4 * (64 * 128);   // 98304
    const int smemF  = (4096 + 4096 + 2048 + 2 * 64 * 68 + 160) * 4 + 128 * 4;

    cudaFuncSetAttribute(conv3_mma<32, true>,  cudaFuncAttributeMaxDynamicSharedMemorySize, smem32);
    cudaFuncSetAttribute(conv3_mma<64, true>,  cudaFuncAttributeMaxDynamicSharedMemorySize, smem64);
    cudaFuncSetAttribute(conv3_mma<64, false>, cudaFuncAttributeMaxDynamicSharedMemorySize, smem64);
    cudaFuncSetAttribute(fused_kernel,         cudaFuncAttributeMaxDynamicSharedMemorySize, smemF);

    reset_kernel<<<1, 32>>>();
    bucket_kernel<<<(M_FINE + 255) / 256, 256>>>(offs);

    convert_feats<<<(N_COARSE * C_IN + 255) / 256, 256>>>(feats, N_COARSE * C_IN, xhi, xlo);
    convert_weights<<<(W_TOT + 255) / 256, 256>>>(We1, We2, We3, wthi, wtlo);

    const int nblk = (N_COARSE + 127) / 128;   // 782
    conv3_mma<32, true ><<<nblk, 256, smem32>>>(xhi,  xlo,  nbr, wthi,          wtlo,          be1, h1hi, h1lo, nullptr);
    conv3_mma<64, true ><<<nblk, 256, smem64>>>(h1hi, h1lo, nbr, wthi + W_OFF1, wtlo + W_OFF1, be2, h2hi, h2lo, nullptr);
    conv3_mma<64, false><<<nblk, 256, smem64>>>(h2hi, h2lo, nbr, wthi + W_OFF2, wtlo + W_OFF2, be3, nullptr, nullptr, pA);

    fused_kernel<<<dim3(128, 8), 256, smemF>>>(pA, parent, Wt, bt, Wd1, bd1,
                                               Wd2, bd2, xup, out);
}

// round 15
// speedup vs baseline: 3.2312x; 1.1021x over previous
#include <cuda_runtime.h>
#include <cuda_bf16.h>
#include <cstdint>

#define N_COARSE 100000
#define M_FINE   400000
#define C_IN     32
#define C_HID    64
#define C_OUT    32
#define K3       27

typedef unsigned long long ull;

// ---------------- scratch (static device globals; no allocation) ----------------
__device__ __nv_bfloat16 g_xhi[N_COARSE * C_IN];
__device__ __nv_bfloat16 g_xlo[N_COARSE * C_IN];
__device__ __nv_bfloat16 g_h1hi[N_COARSE * C_HID];
__device__ __nv_bfloat16 g_h1lo[N_COARSE * C_HID];
__device__ __nv_bfloat16 g_h2hi[N_COARSE * C_HID];
__device__ __nv_bfloat16 g_h2lo[N_COARSE * C_HID];
__device__ __nv_bfloat16 g_h3hi[N_COARSE * C_HID];
__device__ __nv_bfloat16 g_h3lo[N_COARSE * C_HID];
__device__ __nv_bfloat16 g_wthi[3 * K3 * 64 * 64];   // conv weights [layer][k][cin][cout]
__device__ __nv_bfloat16 g_wtlo[3 * K3 * 64 * 64];
__device__ __nv_bfloat16 g_wdhi[10 * 64 * 64];       // Wt(8x64x64) + Wd1(64x64) + Wd2 padded(64x64)
__device__ __nv_bfloat16 g_wdlo[10 * 64 * 64];
__device__ int   g_cnt[8];
__device__ int   g_list[8 * M_FINE];

#define W_OFF1 55296
#define W_OFF2 165888
#define W_TOT  276480
#define WD_D1  32768        // element offset of Wd1 inside g_wd*
#define WD_D2  36864        // element offset of padded Wd2

// ---------------- helpers ----------------
__device__ __forceinline__ unsigned smem_u32(const void* p) {
    return (unsigned)__cvta_generic_to_shared(p);
}
__device__ __forceinline__ void cp_async16(unsigned dst, const void* src, int src_bytes) {
    asm volatile("cp.async.cg.shared.global [%0], [%1], 16, %2;"
                 :: "r"(dst), "l"(src), "r"(src_bytes));
}
__device__ __forceinline__ uint32_t sw128(uint32_t b) { return b ^ ((b >> 3) & 0x70); }

__device__ __forceinline__ void ldsm_x4(uint32_t r[4], uint32_t a) {
    asm volatile("ldmatrix.sync.aligned.m8n8.x4.shared.b16 {%0,%1,%2,%3}, [%4];"
                 : "=r"(r[0]), "=r"(r[1]), "=r"(r[2]), "=r"(r[3]) : "r"(a));
}
__device__ __forceinline__ void ldsm_x2_t(uint32_t r[2], uint32_t a) {
    asm volatile("ldmatrix.sync.aligned.m8n8.x2.trans.shared.b16 {%0,%1}, [%2];"
                 : "=r"(r[0]), "=r"(r[1]) : "r"(a));
}
__device__ __forceinline__ void mma_bf16(float* d, const uint32_t* a, const uint32_t* b) {
    asm volatile("mma.sync.aligned.m16n8k16.row.col.f32.bf16.bf16.f32 "
                 "{%0,%1,%2,%3}, {%4,%5,%6,%7}, {%8,%9}, {%0,%1,%2,%3};"
                 : "+f"(d[0]), "+f"(d[1]), "+f"(d[2]), "+f"(d[3])
                 : "r"(a[0]), "r"(a[1]), "r"(a[2]), "r"(a[3]), "r"(b[0]), "r"(b[1]));
}

// ---------------- pre-pass: split fp32 -> bf16 hi/lo ----------------
__global__ void __launch_bounds__(256)
convert_feats(const float* __restrict__ x, int n,
              __nv_bfloat16* __restrict__ hi, __nv_bfloat16* __restrict__ lo) {
    int i = blockIdx.x * 256 + threadIdx.x;
    if (i < n) {
        float v = x[i];
        __nv_bfloat16 h = __float2bfloat16(v);
        hi[i] = h;
        lo[i] = __float2bfloat16(v - __bfloat162float(h));
    }
}

__global__ void __launch_bounds__(256)
convert_weights(const float* __restrict__ W1, const float* __restrict__ W2,
                const float* __restrict__ W3,
                __nv_bfloat16* __restrict__ hi, __nv_bfloat16* __restrict__ lo) {
    int i = blockIdx.x * 256 + threadIdx.x;
    if (i >= W_TOT) return;
    float v;
    if (i < W_OFF1)      v = W1[i];
    else if (i < W_OFF2) v = W2[i - W_OFF1];
    else                 v = W3[i - W_OFF2];
    __nv_bfloat16 h = __float2bfloat16(v);
    hi[i] = h;
    lo[i] = __float2bfloat16(v - __bfloat162float(h));
}

// decoder weights: Wt [8][64][64] native, Wd1 [64][64], Wd2 [64][32] padded to [64][64]
__global__ void __launch_bounds__(256)
convert_dec_weights(const float* __restrict__ Wt, const float* __restrict__ Wd1,
                    const float* __restrict__ Wd2,
                    __nv_bfloat16* __restrict__ hi, __nv_bfloat16* __restrict__ lo) {
    int i = blockIdx.x * 256 + threadIdx.x;
    if (i >= 10 * 4096) return;
    float v;
    if (i < WD_D1)      v = Wt[i];
    else if (i < WD_D2) v = Wd1[i - WD_D1];
    else {
        int j = i - WD_D2, row = j >> 6, col = j & 63;
        v = (col < 32) ? Wd2[row * 32 + col] : 0.f;
    }
    __nv_bfloat16 h = __float2bfloat16(v);
    hi[i] = h;
    lo[i] = __float2bfloat16(v - __bfloat162float(h));
}

// ---------------- reset + bucket ----------------
__global__ void reset_kernel() {
    if (threadIdx.x < 8) g_cnt[threadIdx.x] = 0;
}

__global__ void __launch_bounds__(256)
bucket_kernel(const int* __restrict__ offs) {
    int m = blockIdx.x * 256 + threadIdx.x;
    unsigned active = __ballot_sync(0xffffffffu, m < M_FINE);
    if (m < M_FINE) {
        int off = offs[m] & 7;
        unsigned mask = __match_any_sync(active, off);
        int lane = threadIdx.x & 31;
        int leader = __ffs(mask) - 1;
        int rank = __popc(mask & ((1u << lane) - 1u));
        int base = 0;
        if (lane == leader) base = atomicAdd(&g_cnt[off], __popc(mask));
        base = __shfl_sync(mask, base, leader);
        g_list[off * M_FINE + base + rank] = m;
    }
}

// ---------------- mma.sync sparse 3x3x3 conv (validated round-9 kernel) ----------------
template <int CIN>
__global__ void __launch_bounds__(256)
conv3_mma(const __nv_bfloat16* __restrict__ xhi, const __nv_bfloat16* __restrict__ xlo,
          const int* __restrict__ nbr,
          const __nv_bfloat16* __restrict__ whi, const __nv_bfloat16* __restrict__ wlo,
          const float* __restrict__ bias,
          __nv_bfloat16* __restrict__ ohi, __nv_bfloat16* __restrict__ olo) {
    constexpr int KSTEPS = CIN / 16;
    constexpr int CH = CIN / 8;
    constexpr int BSZ = CIN * 128;
    extern __shared__ char dsm[];
    const uint32_t sb = smem_u32(dsm);
    const int tid = threadIdx.x, wid = tid >> 5, lane = tid & 31;
    const int vb = blockIdx.x * 128;

    const int arow = tid >> 1, aplane = tid & 1;
    const int gvr = vb + arow;

    auto issue = [&](int k, int buf) {
        int idx = (gvr < N_COARSE) ? __ldg(nbr + gvr * K3 + k) : N_COARSE;
        bool ok = idx < N_COARSE;
        const char* src = (const char*)(aplane ? xlo : xhi) + (size_t)(ok ? idx : 0) * (CIN * 2);
        uint32_t ab = sb + (buf * 2 + aplane) * 16384;
        #pragma unroll
        for (int c = 0; c < CH; ++c)
            cp_async16(ab + sw128(arow * 128 + c * 16), src + c * 16, ok ? 16 : 0);
        #pragma unroll
        for (int r = 0; r < CIN / 16; ++r) {
            int i = tid + 256 * r;
            int brow = i >> 4, q = i & 15, bp = q >> 3, bc = q & 7;
            const char* wsrc = (const char*)(bp ? wlo : whi)
                             + (size_t)k * (CIN * 128) + brow * 128 + bc * 16;
            uint32_t bb = sb + 65536 + (buf * 2 + bp) * BSZ;
            cp_async16(bb + sw128(brow * 128 + bc * 16), wsrc, 16);
        }
        asm volatile("cp.async.commit_group;");
    };

    float acc[8][4];
    #pragma unroll
    for (int t = 0; t < 8; ++t)
        #pragma unroll
        for (int q = 0; q < 4; ++q) acc[t][q] = 0.f;

    const int lr = lane & 7, rb = (lane >> 3) & 1, kb = (lane >> 4) & 1;
    const int amrow = wid * 16 + rb * 8 + lr;
    const int bkl = lane & 15;

    issue(0, 0);
    for (int k = 0; k < K3; ++k) {
        if (k + 1 < K3) {
            issue(k + 1, (k + 1) & 1);
            asm volatile("cp.async.wait_group 1;" ::: "memory");
        } else {
            asm volatile("cp.async.wait_group 0;" ::: "memory");
        }
        __syncthreads();
        const int buf = k & 1;
        const uint32_t ahb = sb + (buf * 2 + 0) * 16384;
        const uint32_t alb = sb + (buf * 2 + 1) * 16384;
        const uint32_t bhb = sb + 65536 + (buf * 2 + 0) * BSZ;
        const uint32_t blb = bhb + BSZ;
        #pragma unroll
        for (int ks = 0; ks < KSTEPS; ++ks) {
            uint32_t abyte = sw128(amrow * 128 + ks * 32 + kb * 16);
            uint32_t ah[4], al[4];
            ldsm_x4(ah, ahb + abyte);
            ldsm_x4(al, alb + abyte);
            int krow = ks * 16 + bkl;
            uint32_t bbase = (uint32_t)krow * 128;
            uint32_t bxor = (uint32_t)(krow & 7) << 4;
            #pragma unroll
            for (int t = 0; t < 8; ++t) {
                uint32_t bb = bbase + ((uint32_t)(t * 16) ^ bxor);
                uint32_t bh[2], bl[2];
                ldsm_x2_t(bh, bhb + bb);
                ldsm_x2_t(bl, blb + bb);
                mma_bf16(acc[t], ah, bh);
                mma_bf16(acc[t], ah, bl);
                mma_bf16(acc[t], al, bh);
            }
        }
        __syncthreads();
    }

    #pragma unroll
    for (int t = 0; t < 8; ++t) {
        #pragma unroll
        for (int h = 0; h < 2; ++h) {
            int r = wid * 16 + (lane >> 2) + h * 8;
            int v = vb + r;
            if (v < N_COARSE) {
                int c = t * 8 + (lane & 3) * 2;
                float a0 = fmaxf(acc[t][h * 2 + 0] + __ldg(bias + c),     0.f);
                float a1 = fmaxf(acc[t][h * 2 + 1] + __ldg(bias + c + 1), 0.f);
                __nv_bfloat16 h0 = __float2bfloat16(a0), h1 = __float2bfloat16(a1);
                __nv_bfloat16 l0 = __float2bfloat16(a0 - __bfloat162float(h0));
                __nv_bfloat16 l1 = __float2bfloat16(a1 - __bfloat162float(h1));
                __nv_bfloat162 hh = __halves2bfloat162(h0, h1);
                __nv_bfloat162 ll = __halves2bfloat162(l0, l1);
                *(__nv_bfloat162*)(ohi + (size_t)v * 64 + c) = hh;
                *(__nv_bfloat162*)(olo + (size_t)v * 64 + c) = ll;
            }
        }
    }
}

// ---------------- fused t-conv + decoder, tensor-core version ----------------
// grid (GX, 8); block = 256 thr / 8 warps; tile = 128 fine voxels; warp = 16 rows.
// smem: A hi/lo 32KB @0 | inter hi/lo 32KB @32768 | Bt 16KB @65536 | B1 16KB @81920
//       | B2 16KB @98304 | biases+lists @114688
#define FM_A     0
#define FM_I     32768
#define FM_BT    65536
#define FM_B1    81920
#define FM_B2    98304
#define FM_BIAS  114688                   // bt[64], bd1[64], bd2[32] floats
#define FM_LIST  (114688 + 640)           // smv[128], spv[128]
#define FM_TOTAL (FM_LIST + 1024)

__global__ void __launch_bounds__(256)
fused_mma(const __nv_bfloat16* __restrict__ h3hi, const __nv_bfloat16* __restrict__ h3lo,
          const int* __restrict__ parent,
          const __nv_bfloat16* __restrict__ wdhi, const __nv_bfloat16* __restrict__ wdlo,
          const float* __restrict__ bt, const float* __restrict__ bd1,
          const float* __restrict__ bd2,
          const float* __restrict__ xup, float* __restrict__ out) {
    extern __shared__ char dsm[];
    const uint32_t sb = smem_u32(dsm);
    const int tid = threadIdx.x, wid = tid >> 5, lane = tid & 31;
    const int off = blockIdx.y;
    const int cnt = g_cnt[off];
    const int* list = g_list + off * M_FINE;

    float* sbias = (float*)(dsm + FM_BIAS);
    int*   smv   = (int*)(dsm + FM_LIST);
    int*   spv   = smv + 128;

    // one-time: decoder weights into smem (hi/lo, SW128) + biases
    {
        #pragma unroll
        for (int r = 0; r < 4; ++r) {                 // Bt: 1024 chunks
            int i = tid + 256 * r;
            int bp = i >> 9, j = i & 511;             // plane, chunk
            const char* src = (const char*)(bp ? wdlo : wdhi) + (size_t)off * 8192 + j * 16;
            cp_async16(sb + FM_BT + bp * 8192 + sw128(j * 16), src, 16);
        }
        #pragma unroll
        for (int r = 0; r < 4; ++r) {                 // B1
            int i = tid + 256 * r;
            int bp = i >> 9, j = i & 511;
            const char* src = (const char*)(bp ? wdlo : wdhi) + (size_t)WD_D1 * 2 + j * 16;
            cp_async16(sb + FM_B1 + bp * 8192 + sw128(j * 16), src, 16);
        }
        #pragma unroll
        for (int r = 0; r < 4; ++r) {                 // B2 (padded)
            int i = tid + 256 * r;
            int bp = i >> 9, j = i & 511;
            const char* src = (const char*)(bp ? wdlo : wdhi) + (size_t)WD_D2 * 2 + j * 16;
            cp_async16(sb + FM_B2 + bp * 8192 + sw128(j * 16), src, 16);
        }
        asm volatile("cp.async.commit_group;");
        if (tid < 64) { sbias[tid] = bt[tid]; sbias[64 + tid] = bd1[tid]; }
        if (tid < 32) sbias[128 + tid] = bd2[tid];
        asm volatile("cp.async.wait_group 0;" ::: "memory");
    }
    __syncthreads();

    const int lr = lane & 7, rb = (lane >> 3) & 1, kb = (lane >> 4) & 1;
    const int amrow = wid * 16 + rb * 8 + lr;
    const int bkl = lane & 15;
    const int crow = lane >> 2, ccol2 = (lane & 3) * 2;

    const int arow = tid >> 1, aplane = tid & 1;      // gather role

    for (int tile = blockIdx.x; tile * 128 < cnt; tile += gridDim.x) {
        __syncthreads();
        if (tid < 128) {
            int j = tile * 128 + tid;
            int m = (j < cnt) ? list[j] : -1;
            smv[tid] = m;
            spv[tid] = (m >= 0) ? parent[m] : N_COARSE;
        }
        __syncthreads();
        // gather parent h3 rows (bf16 hi/lo) into A planes
        {
            int p = spv[arow];
            bool ok = p < N_COARSE;
            const char* src = (const char*)(aplane ? h3lo : h3hi) + (size_t)(ok ? p : 0) * 128;
            uint32_t ab = sb + FM_A + aplane * 16384;
            #pragma unroll
            for (int c = 0; c < 8; ++c)
                cp_async16(ab + sw128(arow * 128 + c * 16), src + c * 16, ok ? 16 : 0);
            asm volatile("cp.async.commit_group;");
            asm volatile("cp.async.wait_group 0;" ::: "memory");
        }
        __syncthreads();

        float acc[8][4];
        // ---- GEMM1: t = A @ Wt[off]; relu(t + bt) -> inter ----
        #pragma unroll
        for (int t = 0; t < 8; ++t)
            #pragma unroll
            for (int q = 0; q < 4; ++q) acc[t][q] = 0.f;
        #pragma unroll
        for (int ks = 0; ks < 4; ++ks) {
            uint32_t abyte = sw128(amrow * 128 + ks * 32 + kb * 16);
            uint32_t ah[4], al[4];
            ldsm_x4(ah, sb + FM_A + abyte);
            ldsm_x4(al, sb + FM_A + 16384 + abyte);
            int krow = ks * 16 + bkl;
            uint32_t bbase = (uint32_t)krow * 128;
            uint32_t bxor = (uint32_t)(krow & 7) << 4;
            #pragma unroll
            for (int t = 0; t < 8; ++t) {
                uint32_t bb = bbase + ((uint32_t)(t * 16) ^ bxor);
                uint32_t bh[2], bl[2];
                ldsm_x2_t(bh, sb + FM_BT + bb);
                ldsm_x2_t(bl, sb + FM_BT + 8192 + bb);
                mma_bf16(acc[t], ah, bh);
                mma_bf16(acc[t], ah, bl);
                mma_bf16(acc[t], al, bh);
            }
        }
        // relu(t + bt) -> split -> inter planes (warp-local rows)
        #pragma unroll
        for (int t = 0; t < 8; ++t) {
            #pragma unroll
            for (int h = 0; h < 2; ++h) {
                int r = wid * 16 + crow + h * 8;
                int c = t * 8 + ccol2;
                float a0 = fmaxf(acc[t][h * 2 + 0] + sbias[c],     0.f);
                float a1 = fmaxf(acc[t][h * 2 + 1] + sbias[c + 1], 0.f);
                __nv_bfloat16 h0 = __float2bfloat16(a0), h1 = __float2bfloat16(a1);
                __nv_bfloat16 l0 = __float2bfloat16(a0 - __bfloat162float(h0));
                __nv_bfloat16 l1 = __float2bfloat16(a1 - __bfloat162float(h1));
                __nv_bfloat162 hh = __halves2bfloat162(h0, h1);
                __nv_bfloat162 ll = __halves2bfloat162(l0, l1);
                uint32_t o = sw128(r * 128 + c * 2);
                *(uint32_t*)(dsm + FM_I + o)         = *(uint32_t*)&hh;
                *(uint32_t*)(dsm + FM_I + 16384 + o) = *(uint32_t*)&ll;
            }
        }
        __syncwarp();

        // ---- GEMM2: y = relu(inter) @ Wd1 -> relu(y+bd1) -> A planes ----
        #pragma unroll
        for (int t = 0; t < 8; ++t)
            #pragma unroll
            for (int q = 0; q < 4; ++q) acc[t][q] = 0.f;
        #pragma unroll
        for (int ks = 0; ks < 4; ++ks) {
            uint32_t abyte = sw128(amrow * 128 + ks * 32 + kb * 16);
            uint32_t ah[4], al[4];
            ldsm_x4(ah, sb + FM_I + abyte);
            ldsm_x4(al, sb + FM_I + 16384 + abyte);
            int krow = ks * 16 + bkl;
            uint32_t bbase = (uint32_t)krow * 128;
            uint32_t bxor = (uint32_t)(krow & 7) << 4;
            #pragma unroll
            for (int t = 0; t < 8; ++t) {
                uint32_t bb = bbase + ((uint32_t)(t * 16) ^ bxor);
                uint32_t bh[2], bl[2];
                ldsm_x2_t(bh, sb + FM_B1 + bb);
                ldsm_x2_t(bl, sb + FM_B1 + 8192 + bb);
                mma_bf16(acc[t], ah, bh);
                mma_bf16(acc[t], ah, bl);
                mma_bf16(acc[t], al, bh);
            }
        }
        #pragma unroll
        for (int t = 0; t < 8; ++t) {
            #pragma unroll
            for (int h = 0; h < 2; ++h) {
                int r = wid * 16 + crow + h * 8;
                int c = t * 8 + ccol2;
                float a0 = fmaxf(acc[t][h * 2 + 0] + sbias[64 + c],     0.f);
                float a1 = fmaxf(acc[t][h * 2 + 1] + sbias[64 + c + 1], 0.f);
                __nv_bfloat16 h0 = __float2bfloat16(a0), h1 = __float2bfloat16(a1);
                __nv_bfloat16 l0 = __float2bfloat16(a0 - __bfloat162float(h0));
                __nv_bfloat16 l1 = __float2bfloat16(a1 - __bfloat162float(h1));
                __nv_bfloat162 hh = __halves2bfloat162(h0, h1);
                __nv_bfloat162 ll = __halves2bfloat162(l0, l1);
                uint32_t o = sw128(r * 128 + c * 2);
                *(uint32_t*)(dsm + FM_A + o)         = *(uint32_t*)&hh;
                *(uint32_t*)(dsm + FM_A + 16384 + o) = *(uint32_t*)&ll;
            }
        }
        __syncwarp();

        // ---- GEMM3: z = relu(y) @ Wd2 + bd2; out = z + xup ----
        float acc3[4][4];
        #pragma unroll
        for (int t = 0; t < 4; ++t)
            #pragma unroll
            for (int q = 0; q < 4; ++q) acc3[t][q] = 0.f;
        #pragma unroll
        for (int ks = 0; ks < 4; ++ks) {
            uint32_t abyte = sw128(amrow * 128 + ks * 32 + kb * 16);
            uint32_t ah[4], al[4];
            ldsm_x4(ah, sb + FM_A + abyte);
            ldsm_x4(al, sb + FM_A + 16384 + abyte);
            int krow = ks * 16 + bkl;
            uint32_t bbase = (uint32_t)krow * 128;
            uint32_t bxor = (uint32_t)(krow & 7) << 4;
            #pragma unroll
            for (int t = 0; t < 4; ++t) {
                uint32_t bb = bbase + ((uint32_t)(t * 16) ^ bxor);
                uint32_t bh[2], bl[2];
                ldsm_x2_t(bh, sb + FM_B2 + bb);
                ldsm_x2_t(bl, sb + FM_B2 + 8192 + bb);
                mma_bf16(acc3[t], ah, bh);
                mma_bf16(acc3[t], ah, bl);
                mma_bf16(acc3[t], al, bh);
            }
        }
        #pragma unroll
        for (int t = 0; t < 4; ++t) {
            #pragma unroll
            for (int h = 0; h < 2; ++h) {
                int r = wid * 16 + crow + h * 8;
                int c = t * 8 + ccol2;
                int m = smv[r];
                if (m >= 0) {
                    float b0 = sbias[128 + c], b1 = sbias[128 + c + 1];
                    const float2 xu = *(const float2*)(xup + (size_t)m * 32 + c);
                    float2 z;
                    z.x = acc3[t][h * 2 + 0] + b0 + xu.x;
                    z.y = acc3[t][h * 2 + 1] + b1 + xu.y;
                    *(float2*)(out + (size_t)m * 32 + c) = z;
                }
            }
        }
    }
}

// ---------------- launch ----------------
extern "C" void kernel_launch(void* const* d_in, const int* in_sizes, int n_in,
                              void* d_out, int out_size) {
    const float* feats  = (const float*)d_in[0];
    const float* xup    = (const float*)d_in[1];
    const int*   nbr    = (const int*)d_in[2];
    const int*   parent = (const int*)d_in[3];
    const int*   offs   = (const int*)d_in[4];
    const float* We1 = (const float*)d_in[5];
    const float* be1 = (const float*)d_in[6];
    const float* We2 = (const float*)d_in[7];
    const float* be2 = (const float*)d_in[8];
    const float* We3 = (const float*)d_in[9];
    const float* be3 = (const float*)d_in[10];
    const float* Wt  = (const float*)d_in[11];
    const float* bt  = (const float*)d_in[12];
    const float* Wd1 = (const float*)d_in[13];
    const float* bd1 = (const float*)d_in[14];
    const float* Wd2 = (const float*)d_in[15];
    const float* bd2 = (const float*)d_in[16];
    float* out = (float*)d_out;

    __nv_bfloat16 *xhi, *xlo, *h1hi, *h1lo, *h2hi, *h2lo, *h3hi, *h3lo;
    __nv_bfloat16 *wthi, *wtlo, *wdhi, *wdlo;
    cudaGetSymbolAddress((void**)&xhi,  g_xhi);
    cudaGetSymbolAddress((void**)&xlo,  g_xlo);
    cudaGetSymbolAddress((void**)&h1hi, g_h1hi);
    cudaGetSymbolAddress((void**)&h1lo, g_h1lo);
    cudaGetSymbolAddress((void**)&h2hi, g_h2hi);
    cudaGetSymbolAddress((void**)&h2lo, g_h2lo);
    cudaGetSymbolAddress((void**)&h3hi, g_h3hi);
    cudaGetSymbolAddress((void**)&h3lo, g_h3lo);
    cudaGetSymbolAddress((void**)&wthi, g_wthi);
    cudaGetSymbolAddress((void**)&wtlo, g_wtlo);
    cudaGetSymbolAddress((void**)&wdhi, g_wdhi);
    cudaGetSymbolAddress((void**)&wdlo, g_wdlo);

    const int smem32 = 65536 + 4 * (32 * 128);   // 81920
    const int smem64 = 65536 + 4 * (64 * 128);   // 98304
    const int smemFM = FM_TOTAL;                 // 116352

    cudaFuncSetAttribute(conv3_mma<32>, cudaFuncAttributeMaxDynamicSharedMemorySize, smem32);
    cudaFuncSetAttribute(conv3_mma<64>, cudaFuncAttributeMaxDynamicSharedMemorySize, smem64);
    cudaFuncSetAttribute(fused_mma,     cudaFuncAttributeMaxDynamicSharedMemorySize, smemFM);

    reset_kernel<<<1, 32>>>();
    bucket_kernel<<<(M_FINE + 255) / 256, 256>>>(offs);

    convert_feats<<<(N_COARSE * C_IN + 255) / 256, 256>>>(feats, N_COARSE * C_IN, xhi, xlo);
    convert_weights<<<(W_TOT + 255) / 256, 256>>>(We1, We2, We3, wthi, wtlo);
    convert_dec_weights<<<(10 * 4096 + 255) / 256, 256>>>(Wt, Wd1, Wd2, wdhi, wdlo);

    const int nblk = (N_COARSE + 127) / 128;   // 782
    conv3_mma<32><<<nblk, 256, smem32>>>(xhi,  xlo,  nbr, wthi,          wtlo,          be1, h1hi, h1lo);
    conv3_mma<64><<<nblk, 256, smem64>>>(h1hi, h1lo, nbr, wthi + W_OFF1, wtlo + W_OFF1, be2, h2hi, h2lo);
    conv3_mma<64><<<nblk, 256, smem64>>>(h2hi, h2lo, nbr, wthi + W_OFF2, wtlo + W_OFF2, be3, h3hi, h3lo);

    fused_mma<<<dim3(64, 8), 256, smemFM>>>(h3hi, h3lo, parent, wdhi, wdlo,
                                            bt, bd1, bd2, xup, out);
}

// round 17
// speedup vs baseline: 3.3412x; 1.0341x over previous
#include <cuda_runtime.h>
#include <cuda_bf16.h>
#include <cstdint>

#define N_COARSE 100000
#define M_FINE   400000
#define C_IN     32
#define C_HID    64
#define C_OUT    32
#define K3       27

typedef unsigned long long ull;

// ---------------- scratch (static device globals; no allocation) ----------------
__device__ __nv_bfloat16 g_xhi[N_COARSE * C_IN];
__device__ __nv_bfloat16 g_xlo[N_COARSE * C_IN];
__device__ __nv_bfloat16 g_h1hi[N_COARSE * C_HID];
__device__ __nv_bfloat16 g_h1lo[N_COARSE * C_HID];
__device__ __nv_bfloat16 g_h2hi[N_COARSE * C_HID];
__device__ __nv_bfloat16 g_h2lo[N_COARSE * C_HID];
__device__ __nv_bfloat16 g_h3hi[N_COARSE * C_HID];
__device__ __nv_bfloat16 g_h3lo[N_COARSE * C_HID];
__device__ __nv_bfloat16 g_wthi[3 * K3 * 64 * 64];   // conv weights [layer][k][cin][cout]
__device__ __nv_bfloat16 g_wtlo[3 * K3 * 64 * 64];
__device__ __nv_bfloat16 g_wdhi[10 * 64 * 64];       // Wt(8x64x64) + Wd1(64x64) + Wd2 padded(64x64)
__device__ __nv_bfloat16 g_wdlo[10 * 64 * 64];
__device__ int   g_cnt[8];
__device__ int   g_list[8 * M_FINE];

#define W_OFF1 55296
#define W_OFF2 165888
#define W_TOT  276480
#define WD_D1  32768        // element offset of Wd1 inside g_wd*
#define WD_D2  36864        // element offset of padded Wd2

// ---------------- helpers ----------------
__device__ __forceinline__ unsigned smem_u32(const void* p) {
    return (unsigned)__cvta_generic_to_shared(p);
}
__device__ __forceinline__ void cp_async16(unsigned dst, const void* src, int src_bytes) {
    asm volatile("cp.async.cg.shared.global [%0], [%1], 16, %2;"
                 :: "r"(dst), "l"(src), "r"(src_bytes));
}
__device__ __forceinline__ uint32_t sw128(uint32_t b) { return b ^ ((b >> 3) & 0x70); }

__device__ __forceinline__ void ldsm_x4(uint32_t r[4], uint32_t a) {
    asm volatile("ldmatrix.sync.aligned.m8n8.x4.shared.b16 {%0,%1,%2,%3}, [%4];"
                 : "=r"(r[0]), "=r"(r[1]), "=r"(r[2]), "=r"(r[3]) : "r"(a));
}
__device__ __forceinline__ void ldsm_x2_t(uint32_t r[2], uint32_t a) {
    asm volatile("ldmatrix.sync.aligned.m8n8.x2.trans.shared.b16 {%0,%1}, [%2];"
                 : "=r"(r[0]), "=r"(r[1]) : "r"(a));
}
__device__ __forceinline__ void mma_bf16(float* d, const uint32_t* a, const uint32_t* b) {
    asm volatile("mma.sync.aligned.m16n8k16.row.col.f32.bf16.bf16.f32 "
                 "{%0,%1,%2,%3}, {%4,%5,%6,%7}, {%8,%9}, {%0,%1,%2,%3};"
                 : "+f"(d[0]), "+f"(d[1]), "+f"(d[2]), "+f"(d[3])
                 : "r"(a[0]), "r"(a[1]), "r"(a[2]), "r"(a[3]), "r"(b[0]), "r"(b[1]));
}

// ---------------- pre-pass: split fp32 -> bf16 hi/lo ----------------
__global__ void __launch_bounds__(256)
convert_feats(const float* __restrict__ x, int n,
              __nv_bfloat16* __restrict__ hi, __nv_bfloat16* __restrict__ lo) {
    int i = blockIdx.x * 256 + threadIdx.x;
    if (i < n) {
        float v = x[i];
        __nv_bfloat16 h = __float2bfloat16(v);
        hi[i] = h;
        lo[i] = __float2bfloat16(v - __bfloat162float(h));
    }
}

__global__ void __launch_bounds__(256)
convert_weights(const float* __restrict__ W1, const float* __restrict__ W2,
                const float* __restrict__ W3,
                __nv_bfloat16* __restrict__ hi, __nv_bfloat16* __restrict__ lo) {
    int i = blockIdx.x * 256 + threadIdx.x;
    if (i >= W_TOT) return;
    float v;
    if (i < W_OFF1)      v = W1[i];
    else if (i < W_OFF2) v = W2[i - W_OFF1];
    else                 v = W3[i - W_OFF2];
    __nv_bfloat16 h = __float2bfloat16(v);
    hi[i] = h;
    lo[i] = __float2bfloat16(v - __bfloat162float(h));
}

// decoder weights: Wt [8][64][64] native, Wd1 [64][64], Wd2 [64][32] padded to [64][64]
__global__ void __launch_bounds__(256)
convert_dec_weights(const float* __restrict__ Wt, const float* __restrict__ Wd1,
                    const float* __restrict__ Wd2,
                    __nv_bfloat16* __restrict__ hi, __nv_bfloat16* __restrict__ lo) {
    int i = blockIdx.x * 256 + threadIdx.x;
    if (i >= 10 * 4096) return;
    float v;
    if (i < WD_D1)      v = Wt[i];
    else if (i < WD_D2) v = Wd1[i - WD_D1];
    else {
        int j = i - WD_D2, row = j >> 6, col = j & 63;
        v = (col < 32) ? Wd2[row * 32 + col] : 0.f;
    }
    __nv_bfloat16 h = __float2bfloat16(v);
    hi[i] = h;
    lo[i] = __float2bfloat16(v - __bfloat162float(h));
}

// ---------------- reset + bucket ----------------
__global__ void reset_kernel() {
    if (threadIdx.x < 8) g_cnt[threadIdx.x] = 0;
}

__global__ void __launch_bounds__(256)
bucket_kernel(const int* __restrict__ offs) {
    int m = blockIdx.x * 256 + threadIdx.x;
    unsigned active = __ballot_sync(0xffffffffu, m < M_FINE);
    if (m < M_FINE) {
        int off = offs[m] & 7;
        unsigned mask = __match_any_sync(active, off);
        int lane = threadIdx.x & 31;
        int leader = __ffs(mask) - 1;
        int rank = __popc(mask & ((1u << lane) - 1u));
        int base = 0;
        if (lane == leader) base = atomicAdd(&g_cnt[off], __popc(mask));
        base = __shfl_sync(mask, base, leader);
        g_list[off * M_FINE + base + rank] = m;
    }
}

// ---------------- mma.sync sparse 3x3x3 conv (validated round-9 kernel) ----------------
template <int CIN>
__global__ void __launch_bounds__(256)
conv3_mma(const __nv_bfloat16* __restrict__ xhi, const __nv_bfloat16* __restrict__ xlo,
          const int* __restrict__ nbr,
          const __nv_bfloat16* __restrict__ whi, const __nv_bfloat16* __restrict__ wlo,
          const float* __restrict__ bias,
          __nv_bfloat16* __restrict__ ohi, __nv_bfloat16* __restrict__ olo) {
    constexpr int KSTEPS = CIN / 16;
    constexpr int CH = CIN / 8;
    constexpr int BSZ = CIN * 128;
    extern __shared__ char dsm[];
    const uint32_t sb = smem_u32(dsm);
    const int tid = threadIdx.x, wid = tid >> 5, lane = tid & 31;
    const int vb = blockIdx.x * 128;

    const int arow = tid >> 1, aplane = tid & 1;
    const int gvr = vb + arow;

    auto issue = [&](int k, int buf) {
        int idx = (gvr < N_COARSE) ? __ldg(nbr + gvr * K3 + k) : N_COARSE;
        bool ok = idx < N_COARSE;
        const char* src = (const char*)(aplane ? xlo : xhi) + (size_t)(ok ? idx : 0) * (CIN * 2);
        uint32_t ab = sb + (buf * 2 + aplane) * 16384;
        #pragma unroll
        for (int c = 0; c < CH; ++c)
            cp_async16(ab + sw128(arow * 128 + c * 16), src + c * 16, ok ? 16 : 0);
        #pragma unroll
        for (int r = 0; r < CIN / 16; ++r) {
            int i = tid + 256 * r;
            int brow = i >> 4, q = i & 15, bp = q >> 3, bc = q & 7;
            const char* wsrc = (const char*)(bp ? wlo : whi)
                             + (size_t)k * (CIN * 128) + brow * 128 + bc * 16;
            uint32_t bb = sb + 65536 + (buf * 2 + bp) * BSZ;
            cp_async16(bb + sw128(brow * 128 + bc * 16), wsrc, 16);
        }
        asm volatile("cp.async.commit_group;");
    };

    float acc[8][4];
    #pragma unroll
    for (int t = 0; t < 8; ++t)
        #pragma unroll
        for (int q = 0; q < 4; ++q) acc[t][q] = 0.f;

    const int lr = lane & 7, rb = (lane >> 3) & 1, kb = (lane >> 4) & 1;
    const int amrow = wid * 16 + rb * 8 + lr;
    const int bkl = lane & 15;

    issue(0, 0);
    for (int k = 0; k < K3; ++k) {
        if (k + 1 < K3) {
            issue(k + 1, (k + 1) & 1);
            asm volatile("cp.async.wait_group 1;" ::: "memory");
        } else {
            asm volatile("cp.async.wait_group 0;" ::: "memory");
        }
        __syncthreads();
        const int buf = k & 1;
        const uint32_t ahb = sb + (buf * 2 + 0) * 16384;
        const uint32_t alb = sb + (buf * 2 + 1) * 16384;
        const uint32_t bhb = sb + 65536 + (buf * 2 + 0) * BSZ;
        const uint32_t blb = bhb + BSZ;
        #pragma unroll
        for (int ks = 0; ks < KSTEPS; ++ks) {
            uint32_t abyte = sw128(amrow * 128 + ks * 32 + kb * 16);
            uint32_t ah[4], al[4];
            ldsm_x4(ah, ahb + abyte);
            ldsm_x4(al, alb + abyte);
            int krow = ks * 16 + bkl;
            uint32_t bbase = (uint32_t)krow * 128;
            uint32_t bxor = (uint32_t)(krow & 7) << 4;
            #pragma unroll
            for (int t = 0; t < 8; ++t) {
                uint32_t bb = bbase + ((uint32_t)(t * 16) ^ bxor);
                uint32_t bh[2], bl[2];
                ldsm_x2_t(bh, bhb + bb);
                ldsm_x2_t(bl, blb + bb);
                mma_bf16(acc[t], ah, bh);
                mma_bf16(acc[t], ah, bl);
                mma_bf16(acc[t], al, bh);
            }
        }
        __syncthreads();
    }

    #pragma unroll
    for (int t = 0; t < 8; ++t) {
        #pragma unroll
        for (int h = 0; h < 2; ++h) {
            int r = wid * 16 + (lane >> 2) + h * 8;
            int v = vb + r;
            if (v < N_COARSE) {
                int c = t * 8 + (lane & 3) * 2;
                float a0 = fmaxf(acc[t][h * 2 + 0] + __ldg(bias + c),     0.f);
                float a1 = fmaxf(acc[t][h * 2 + 1] + __ldg(bias + c + 1), 0.f);
                __nv_bfloat16 h0 = __float2bfloat16(a0), h1 = __float2bfloat16(a1);
                __nv_bfloat16 l0 = __float2bfloat16(a0 - __bfloat162float(h0));
                __nv_bfloat16 l1 = __float2bfloat16(a1 - __bfloat162float(h1));
                __nv_bfloat162 hh = __halves2bfloat162(h0, h1);
                __nv_bfloat162 ll = __halves2bfloat162(l0, l1);
                *(__nv_bfloat162*)(ohi + (size_t)v * 64 + c) = hh;
                *(__nv_bfloat162*)(olo + (size_t)v * 64 + c) = ll;
            }
        }
    }
}

// ---------------- fused t-conv + decoder, tensor-core version (gather double-buffered) ----------------
// grid (GX, 8); block = 256 thr / 8 warps; tile = 128 fine voxels; warp = 16 rows.
// smem: A0 hi/lo 32KB @0 | A1 hi/lo 32KB @32768 | I hi/lo 32KB @65536 |
//       Bt 16KB @98304 | B1 16KB @114688 | B2 16KB @131072 | biases @147456
#define FM_A0    0
#define FM_A1    32768
#define FM_I     65536
#define FM_BT    98304
#define FM_B1    114688
#define FM_B2    131072
#define FM_BIAS  147456                   // bt[64], bd1[64], bd2[32] floats
#define FM_TOTAL (FM_BIAS + 640)

__global__ void __launch_bounds__(256)
fused_mma(const __nv_bfloat16* __restrict__ h3hi, const __nv_bfloat16* __restrict__ h3lo,
          const int* __restrict__ parent,
          const __nv_bfloat16* __restrict__ wdhi, const __nv_bfloat16* __restrict__ wdlo,
          const float* __restrict__ bt, const float* __restrict__ bd1,
          const float* __restrict__ bd2,
          const float* __restrict__ xup, float* __restrict__ out) {
    extern __shared__ char dsm[];
    const uint32_t sb = smem_u32(dsm);
    const int tid = threadIdx.x, wid = tid >> 5, lane = tid & 31;
    const int off = blockIdx.y;
    const int cnt = g_cnt[off];
    const int* list = g_list + off * M_FINE;

    float* sbias = (float*)(dsm + FM_BIAS);

    // one-time: decoder weights into smem (hi/lo, SW128) + biases
    {
        #pragma unroll
        for (int r = 0; r < 4; ++r) {                 // Bt: 1024 chunks
            int i = tid + 256 * r;
            int bp = i >> 9, j = i & 511;             // plane, chunk
            const char* src = (const char*)(bp ? wdlo : wdhi) + (size_t)off * 8192 + j * 16;
            cp_async16(sb + FM_BT + bp * 8192 + sw128(j * 16), src, 16);
        }
        #pragma unroll
        for (int r = 0; r < 4; ++r) {                 // B1
            int i = tid + 256 * r;
            int bp = i >> 9, j = i & 511;
            const char* src = (const char*)(bp ? wdlo : wdhi) + (size_t)WD_D1 * 2 + j * 16;
            cp_async16(sb + FM_B1 + bp * 8192 + sw128(j * 16), src, 16);
        }
        #pragma unroll
        for (int r = 0; r < 4; ++r) {                 // B2 (padded)
            int i = tid + 256 * r;
            int bp = i >> 9, j = i & 511;
            const char* src = (const char*)(bp ? wdlo : wdhi) + (size_t)WD_D2 * 2 + j * 16;
            cp_async16(sb + FM_B2 + bp * 8192 + sw128(j * 16), src, 16);
        }
        asm volatile("cp.async.commit_group;");
        if (tid < 64) { sbias[tid] = bt[tid]; sbias[64 + tid] = bd1[tid]; }
        if (tid < 32) sbias[128 + tid] = bd2[tid];
        asm volatile("cp.async.wait_group 0;" ::: "memory");
    }
    __syncthreads();

    const int lr = lane & 7, rb = (lane >> 3) & 1, kb = (lane >> 4) & 1;
    const int amrow = wid * 16 + rb * 8 + lr;
    const int bkl = lane & 15;
    const int crow = lane >> 2, ccol2 = (lane & 3) * 2;

    const int arow = tid >> 1, aplane = tid & 1;      // gather role

    // issue gather for a tile's 128 parent rows into A buffer abuf (garbage rows
    // beyond cnt are left as-is: row-independent GEMMs, outputs guarded).
    auto gather = [&](int tl, int abuf) {
        int j = tl * 128 + arow;
        int p = N_COARSE;
        if (j < cnt) {
            int m = __ldg(list + j);
            p = __ldg(parent + m);
        }
        bool ok = p < N_COARSE;
        const char* src = (const char*)(aplane ? h3lo : h3hi) + (size_t)(ok ? p : 0) * 128;
        uint32_t ab = sb + (abuf ? FM_A1 : FM_A0) + aplane * 16384;
        #pragma unroll
        for (int c = 0; c < 8; ++c)
            cp_async16(ab + sw128(arow * 128 + c * 16), src + c * 16, ok ? 16 : 0);
        asm volatile("cp.async.commit_group;");
    };

    if ((int)blockIdx.x * 128 >= cnt) return;   // no tiles for this block
    gather(blockIdx.x, 0);                       // prologue gather tile0 -> A0

    int abuf = 0;
    for (int tile = blockIdx.x; tile * 128 < cnt; tile += gridDim.x, abuf ^= 1) {
        asm volatile("cp.async.wait_group 0;" ::: "memory");
        __syncthreads();
        // overlap next tile's gather with this tile's 3 GEMMs
        int ntile = tile + gridDim.x;
        if (ntile * 128 < cnt) gather(ntile, abuf ^ 1);

        const uint32_t fa = sb + (abuf ? FM_A1 : FM_A0);

        float acc[8][4];
        // ---- GEMM1: t = A @ Wt[off]; relu(t + bt) -> I ----
        #pragma unroll
        for (int t = 0; t < 8; ++t)
            #pragma unroll
            for (int q = 0; q < 4; ++q) acc[t][q] = 0.f;
        #pragma unroll
        for (int ks = 0; ks < 4; ++ks) {
            uint32_t abyte = sw128(amrow * 128 + ks * 32 + kb * 16);
            uint32_t ah[4], al[4];
            ldsm_x4(ah, fa + abyte);
            ldsm_x4(al, fa + 16384 + abyte);
            int krow = ks * 16 + bkl;
            uint32_t bbase = (uint32_t)krow * 128;
            uint32_t bxor = (uint32_t)(krow & 7) << 4;
            #pragma unroll
            for (int t = 0; t < 8; ++t) {
                uint32_t bb = bbase + ((uint32_t)(t * 16) ^ bxor);
                uint32_t bh[2], bl[2];
                ldsm_x2_t(bh, sb + FM_BT + bb);
                ldsm_x2_t(bl, sb + FM_BT + 8192 + bb);
                mma_bf16(acc[t], ah, bh);
                mma_bf16(acc[t], ah, bl);
                mma_bf16(acc[t], al, bh);
            }
        }
        #pragma unroll
        for (int t = 0; t < 8; ++t) {
            #pragma unroll
            for (int h = 0; h < 2; ++h) {
                int r = wid * 16 + crow + h * 8;
                int c = t * 8 + ccol2;
                float a0 = fmaxf(acc[t][h * 2 + 0] + sbias[c],     0.f);
                float a1 = fmaxf(acc[t][h * 2 + 1] + sbias[c + 1], 0.f);
                __nv_bfloat16 h0 = __float2bfloat16(a0), h1 = __float2bfloat16(a1);
                __nv_bfloat16 l0 = __float2bfloat16(a0 - __bfloat162float(h0));
                __nv_bfloat16 l1 = __float2bfloat16(a1 - __bfloat162float(h1));
                __nv_bfloat162 hh = __halves2bfloat162(h0, h1);
                __nv_bfloat162 ll = __halves2bfloat162(l0, l1);
                uint32_t o = sw128(r * 128 + c * 2);
                *(uint32_t*)(dsm + FM_I + o)         = *(uint32_t*)&hh;
                *(uint32_t*)(dsm + FM_I + 16384 + o) = *(uint32_t*)&ll;
            }
        }
        __syncwarp();

        // ---- GEMM2: y = relu(t) @ Wd1 -> relu(y+bd1) -> I (read-then-overwrite, warp-local) ----
        #pragma unroll
        for (int t = 0; t < 8; ++t)
            #pragma unroll
            for (int q = 0; q < 4; ++q) acc[t][q] = 0.f;
        #pragma unroll
        for (int ks = 0; ks < 4; ++ks) {
            uint32_t abyte = sw128(amrow * 128 + ks * 32 + kb * 16);
            uint32_t ah[4], al[4];
            ldsm_x4(ah, sb + FM_I + abyte);
            ldsm_x4(al, sb + FM_I + 16384 + abyte);
            int krow = ks * 16 + bkl;
            uint32_t bbase = (uint32_t)krow * 128;
            uint32_t bxor = (uint32_t)(krow & 7) << 4;
            #pragma unroll
            for (int t = 0; t < 8; ++t) {
                uint32_t bb = bbase + ((uint32_t)(t * 16) ^ bxor);
                uint32_t bh[2], bl[2];
                ldsm_x2_t(bh, sb + FM_B1 + bb);
                ldsm_x2_t(bl, sb + FM_B1 + 8192 + bb);
                mma_bf16(acc[t], ah, bh);
                mma_bf16(acc[t], ah, bl);
                mma_bf16(acc[t], al, bh);
            }
        }
        __syncwarp();   // all GEMM2 reads of I complete before overwrite
        #pragma unroll
        for (int t = 0; t < 8; ++t) {
            #pragma unroll
            for (int h = 0; h < 2; ++h) {
                int r = wid * 16 + crow + h * 8;
                int c = t * 8 + ccol2;
                float a0 = fmaxf(acc[t][h * 2 + 0] + sbias[64 + c],     0.f);
                float a1 = fmaxf(acc[t][h * 2 + 1] + sbias[64 + c + 1], 0.f);
                __nv_bfloat16 h0 = __float2bfloat16(a0), h1 = __float2bfloat16(a1);
                __nv_bfloat16 l0 = __float2bfloat16(a0 - __bfloat162float(h0));
                __nv_bfloat16 l1 = __float2bfloat16(a1 - __bfloat162float(h1));
                __nv_bfloat162 hh = __halves2bfloat162(h0, h1);
                __nv_bfloat162 ll = __halves2bfloat162(l0, l1);
                uint32_t o = sw128(r * 128 + c * 2);
                *(uint32_t*)(dsm + FM_I + o)         = *(uint32_t*)&hh;
                *(uint32_t*)(dsm + FM_I + 16384 + o) = *(uint32_t*)&ll;
            }
        }
        __syncwarp();

        // ---- GEMM3: z = y @ Wd2 + bd2; out = z + xup ----
        float acc3[4][4];
        #pragma unroll
        for (int t = 0; t < 4; ++t)
            #pragma unroll
            for (int q = 0; q < 4; ++q) acc3[t][q] = 0.f;
        #pragma unroll
        for (int ks = 0; ks < 4; ++ks) {
            uint32_t abyte = sw128(amrow * 128 + ks * 32 + kb * 16);
            uint32_t ah[4], al[4];
            ldsm_x4(ah, sb + FM_I + abyte);
            ldsm_x4(al, sb + FM_I + 16384 + abyte);
            int krow = ks * 16 + bkl;
            uint32_t bbase = (uint32_t)krow * 128;
            uint32_t bxor = (uint32_t)(krow & 7) << 4;
            #pragma unroll
            for (int t = 0; t < 4; ++t) {
                uint32_t bb = bbase + ((uint32_t)(t * 16) ^ bxor);
                uint32_t bh[2], bl[2];
                ldsm_x2_t(bh, sb + FM_B2 + bb);
                ldsm_x2_t(bl, sb + FM_B2 + 8192 + bb);
                mma_bf16(acc3[t], ah, bh);
                mma_bf16(acc3[t], ah, bl);
                mma_bf16(acc3[t], al, bh);
            }
        }
        #pragma unroll
        for (int t = 0; t < 4; ++t) {
            #pragma unroll
            for (int h = 0; h < 2; ++h) {
                int r = wid * 16 + crow + h * 8;
                int jr = tile * 128 + r;
                int m = (jr < cnt) ? __ldg(list + jr) : -1;
                int c = t * 8 + ccol2;
                if (m >= 0) {
                    float b0 = sbias[128 + c], b1 = sbias[128 + c + 1];
                    const float2 xu = *(const float2*)(xup + (size_t)m * 32 + c);
                    float2 z;
                    z.x = acc3[t][h * 2 + 0] + b0 + xu.x;
                    z.y = acc3[t][h * 2 + 1] + b1 + xu.y;
                    *(float2*)(out + (size_t)m * 32 + c) = z;
                }
            }
        }
    }
}

// ---------------- launch ----------------
extern "C" void kernel_launch(void* const* d_in, const int* in_sizes, int n_in,
                              void* d_out, int out_size) {
    const float* feats  = (const float*)d_in[0];
    const float* xup    = (const float*)d_in[1];
    const int*   nbr    = (const int*)d_in[2];
    const int*   parent = (const int*)d_in[3];
    const int*   offs   = (const int*)d_in[4];
    const float* We1 = (const float*)d_in[5];
    const float* be1 = (const float*)d_in[6];
    const float* We2 = (const float*)d_in[7];
    const float* be2 = (const float*)d_in[8];
    const float* We3 = (const float*)d_in[9];
    const float* be3 = (const float*)d_in[10];
    const float* Wt  = (const float*)d_in[11];
    const float* bt  = (const float*)d_in[12];
    const float* Wd1 = (const float*)d_in[13];
    const float* bd1 = (const float*)d_in[14];
    const float* Wd2 = (const float*)d_in[15];
    const float* bd2 = (const float*)d_in[16];
    float* out = (float*)d_out;

    __nv_bfloat16 *xhi, *xlo, *h1hi, *h1lo, *h2hi, *h2lo, *h3hi, *h3lo;
    __nv_bfloat16 *wthi, *wtlo, *wdhi, *wdlo;
    cudaGetSymbolAddress((void**)&xhi,  g_xhi);
    cudaGetSymbolAddress((void**)&xlo,  g_xlo);
    cudaGetSymbolAddress((void**)&h1hi, g_h1hi);
    cudaGetSymbolAddress((void**)&h1lo, g_h1lo);
    cudaGetSymbolAddress((void**)&h2hi, g_h2hi);
    cudaGetSymbolAddress((void**)&h2lo, g_h2lo);
    cudaGetSymbolAddress((void**)&h3hi, g_h3hi);
    cudaGetSymbolAddress((void**)&h3lo, g_h3lo);
    cudaGetSymbolAddress((void**)&wthi, g_wthi);
    cudaGetSymbolAddress((void**)&wtlo, g_wtlo);
    cudaGetSymbolAddress((void**)&wdhi, g_wdhi);
    cudaGetSymbolAddress((void**)&wdlo, g_wdlo);

    const int smem32 = 65536 + 4 * (32 * 128);   // 81920
    const int smem64 = 65536 + 4 * (64 * 128);   // 98304
    const int smemFM = FM_TOTAL;                 // 148096

    cudaFuncSetAttribute(conv3_mma<32>, cudaFuncAttributeMaxDynamicSharedMemorySize, smem32);
    cudaFuncSetAttribute(conv3_mma<64>, cudaFuncAttributeMaxDynamicSharedMemorySize, smem64);
    cudaFuncSetAttribute(fused_mma,     cudaFuncAttributeMaxDynamicSharedMemorySize, smemFM);

    reset_kernel<<<1, 32>>>();
    bucket_kernel<<<(M_FINE + 255) / 256, 256>>>(offs);

    convert_feats<<<(N_COARSE * C_IN + 255) / 256, 256>>>(feats, N_COARSE * C_IN, xhi, xlo);
    convert_weights<<<(W_TOT + 255) / 256, 256>>>(We1, We2, We3, wthi, wtlo);
    convert_dec_weights<<<(10 * 4096 + 255) / 256, 256>>>(Wt, Wd1, Wd2, wdhi, wdlo);

    const int nblk = (N_COARSE + 127) / 128;   // 782
    conv3_mma<32><<<nblk, 256, smem32>>>(xhi,  xlo,  nbr, wthi,          wtlo,          be1, h1hi, h1lo);
    conv3_mma<64><<<nblk, 256, smem64>>>(h1hi, h1lo, nbr, wthi + W_OFF1, wtlo + W_OFF1, be2, h2hi, h2lo);
    conv3_mma<64><<<nblk, 256, smem64>>>(h2hi, h2lo, nbr, wthi + W_OFF2, wtlo + W_OFF2, be3, h3hi, h3lo);

    fused_mma<<<dim3(64, 8), 256, smemFM>>>(h3hi, h3lo, parent, wdhi, wdlo,
                                            bt, bd1, bd2, xup, out);
}